// round 11
// baseline (speedup 1.0000x reference)
#include <cuda_runtime.h>
#include <math.h>

// Problem constants (b=2,h=8,n=4096,d=64,m=256)
#define BHN   16
#define NSEQ  4096
#define DDIM  64
#define MDIM  256
#define LCOND 256
#define NCHUNK 128
#define LCH   30
#define EDIM  64
#define NSLOT 129         // cond(0) + 128 causal chunks

#define NORMALIZER 0.35355339059327373f  // 64^-0.25
#define DIAGC      0.0625f               // 0.5 * normalizer^2
#define RATIO      0.0625f               // 256^-0.5
#define EPSK       1e-4f
#define EPSC       1e-6f

// packed f32x2 helpers (Blackwell FFMA2 path)
#define FMA2(acc, a, b)  asm("fma.rn.f32x2 %0, %1, %2, %0;" : "+l"(acc) : "l"(a), "l"(b))
#define PACK2(d, x, y)   asm("mov.b64 %0, {%1, %2};" : "=l"(d) : "f"(x), "f"(y))
#define UNPACK2(x, y, s) asm("mov.b64 {%0, %1}, %2;" : "=f"(x), "=f"(y) : "l"(s))

// ---------------- scratch (static device globals; allocation-free) -----------
__device__ float g_QP[(size_t)BHN * NSEQ * MDIM];            // 64 MB  qp (final)
__device__ float g_KE[(size_t)BHN * NSEQ * MDIM];            // 64 MB  E = exp(dash-diag)
__device__ unsigned g_kmax;
__device__ float g_Lk  [(size_t)BHN * NSLOT * MDIM];
__device__ float g_Lctx[(size_t)BHN * NSLOT * MDIM * EDIM];  // 135 MB (carries)

__device__ __forceinline__ unsigned ford(float f) {
    unsigned u = __float_as_uint(f);
    return (u & 0x80000000u) ? ~u : (u | 0x80000000u);
}
__device__ __forceinline__ float fuord(unsigned u) {
    return (u & 0x80000000u) ? __uint_as_float(u ^ 0x80000000u)
                             : __uint_as_float(~u);
}

__global__ void init_kernel() { g_kmax = 0u; }

// ---------------- feature map:  dash = norm * (X @ projT), packed f32x2 ------
template <bool IS_Q>
__global__ __launch_bounds__(256) void feat_kernel(const float* __restrict__ data,
                                                   const float* __restrict__ proj) {
    __shared__ float qt[64 * 20];       // 5.1 KB transposed tile
    __shared__ float red[8 * 16];
    __shared__ float diag_s[16];
    __shared__ float rmax_s[16];

    const int tid  = threadIdx.x;
    const int lane = tid & 31, wid = tid >> 5;
    const size_t row0 = (size_t)blockIdx.x * 16;

    float4 pr[16];                       // this thread's proj row (64 floats)
#pragma unroll
    for (int i = 0; i < 16; i++) pr[i] = *(const float4*)&proj[tid * 64 + i * 4];

    for (int idx = tid; idx < 16 * 64; idx += 256) {
        int r = idx >> 6, d = idx & 63;
        qt[d * 20 + r] = data[(row0 + r) * 64 + d];
    }
    __syncthreads();

    if (tid < 16) {
        float s = 0.f;
        for (int d = 0; d < 64; d++) { float x = qt[d * 20 + tid]; s += x * x; }
        diag_s[tid] = s * DIAGC;
    }
    __syncthreads();

    unsigned long long accp[8];
#pragma unroll
    for (int t = 0; t < 8; t++) accp[t] = 0ull;

#pragma unroll
    for (int d = 0; d < 64; d++) {
        float pd = ((d & 3) == 0) ? pr[d >> 2].x :
                   ((d & 3) == 1) ? pr[d >> 2].y :
                   ((d & 3) == 2) ? pr[d >> 2].z : pr[d >> 2].w;
        unsigned long long pp; PACK2(pp, pd, pd);
        ulonglong2 q0 = *(const ulonglong2*)&qt[d * 20 + 0];    // rows (0,1),(2,3)
        ulonglong2 q1 = *(const ulonglong2*)&qt[d * 20 + 4];
        ulonglong2 q2 = *(const ulonglong2*)&qt[d * 20 + 8];
        ulonglong2 q3 = *(const ulonglong2*)&qt[d * 20 + 12];
        FMA2(accp[0], q0.x, pp); FMA2(accp[1], q0.y, pp);
        FMA2(accp[2], q1.x, pp); FMA2(accp[3], q1.y, pp);
        FMA2(accp[4], q2.x, pp); FMA2(accp[5], q2.y, pp);
        FMA2(accp[6], q3.x, pp); FMA2(accp[7], q3.y, pp);
    }

    float dash[16];
#pragma unroll
    for (int t = 0; t < 8; t++) UNPACK2(dash[2 * t], dash[2 * t + 1], accp[t]);
#pragma unroll
    for (int r = 0; r < 16; r++) dash[r] *= NORMALIZER;

    if (IS_Q) {
#pragma unroll
        for (int r = 0; r < 16; r++) {
            float v = dash[r];
            for (int off = 16; off; off >>= 1)
                v = fmaxf(v, __shfl_xor_sync(0xffffffffu, v, off));
            if (lane == 0) red[wid * 16 + r] = v;
        }
        __syncthreads();
        if (tid < 16) {
            float m = red[tid];
            for (int w = 1; w < 8; w++) m = fmaxf(m, red[w * 16 + tid]);
            rmax_s[tid] = m;
        }
        __syncthreads();
#pragma unroll
        for (int r = 0; r < 16; r++)
            g_QP[(row0 + r) * 256 + tid] =
                RATIO * (__expf(dash[r] - diag_s[r] - rmax_s[r]) + EPSK);
    } else {
        float bm = dash[0];
#pragma unroll
        for (int r = 1; r < 16; r++) bm = fmaxf(bm, dash[r]);
        for (int off = 16; off; off >>= 1)
            bm = fmaxf(bm, __shfl_xor_sync(0xffffffffu, bm, off));
        if (lane == 0) red[wid] = bm;
        __syncthreads();
        if (tid == 0) {
            float m = red[0];
            for (int w = 1; w < 8; w++) m = fmaxf(m, red[w]);
            atomicMax(&g_kmax, ford(m));
        }
#pragma unroll
        for (int r = 0; r < 16; r++)
            g_KE[(row0 + r) * 256 + tid] = __expf(dash[r] - diag_s[r]);   // E
    }
}

// ---------------- fused chunk-sums + exclusive prefix ------------------------
// grid (8 m-blocks, BHN); block 256 = e(64) x mg2(4). Block owns (bh, 32 m's,
// all 64 e) and walks slots sequentially, carry in registers: 4 packed m-pair
// accs per thread. Lctx/Lk written ONCE with the exclusive-prefix carries.
__global__ __launch_bounds__(256) void fused_sums_kernel(const float* __restrict__ v) {
    __shared__ float kp_s[32 * 32];     // 4 KB  (<=32 rows x 32 m)
    __shared__ float v_s[32 * 64];      // 8 KB

    const int tid = threadIdx.x;
    const int e = tid & 63, mg2 = tid >> 6;     // mg2 uniform per warp
    const int m0 = blockIdx.x * 32;
    const int bh = blockIdx.y;
    const float gmax = fuord(g_kmax);
    const float rs = RATIO * __expf(-gmax);
    const float rk = RATIO * EPSK;

    const float* Eb = g_KE + (size_t)bh * NSEQ * 256;
    const float* vb = v    + (size_t)bh * NSEQ * 64;
    float* Lc = g_Lctx + (size_t)bh * NSLOT * 16384;
    float* Lk = g_Lk   + (size_t)bh * NSLOT * 256;

    unsigned long long acc[4];
#pragma unroll
    for (int c = 0; c < 4; c++) acc[c] = 0ull;
    float lkacc = 0.f;                           // tid<32: m = m0+tid

    // ---- slot 0 (cond): 256 rows in 8 tiles of 32
    for (int base = 0; base < LCOND; base += 32) {
        __syncthreads();
        for (int idx = tid; idx < 32 * 32; idx += 256) {
            int row = idx >> 5, mc = idx & 31;
            kp_s[idx] = fmaf(Eb[(size_t)(base + row) * 256 + m0 + mc], rs, rk);
        }
        for (int idx = tid; idx < 32 * 64; idx += 256)
            v_s[idx] = vb[(size_t)base * 64 + idx];
        __syncthreads();
#pragma unroll 4
        for (int row = 0; row < 32; row++) {
            float vsc = v_s[row * 64 + e];
            unsigned long long vv; PACK2(vv, vsc, vsc);
            const float* kr = &kp_s[row * 32 + mg2 * 8];       // broadcast
            ulonglong2 k01 = *(const ulonglong2*)&kr[0];
            ulonglong2 k23 = *(const ulonglong2*)&kr[4];
            FMA2(acc[0], k01.x, vv); FMA2(acc[1], k01.y, vv);
            FMA2(acc[2], k23.x, vv); FMA2(acc[3], k23.y, vv);
        }
        if (tid < 32) {
#pragma unroll 8
            for (int row = 0; row < 32; row++) lkacc += kp_s[row * 32 + tid];
        }
    }
    // write Lctx[0] and Lctx[1] (both = slot-0 sum), likewise Lk
    {
        size_t ob = (size_t)(m0 + mg2 * 8) * 64 + e;
#pragma unroll
        for (int p = 0; p < 4; p++) {
            float lo, hi; UNPACK2(lo, hi, acc[p]);
            Lc[ob + (size_t)(2 * p    ) * 64] = lo;
            Lc[ob + (size_t)(2 * p + 1) * 64] = hi;
            Lc[16384 + ob + (size_t)(2 * p    ) * 64] = lo;
            Lc[16384 + ob + (size_t)(2 * p + 1) * 64] = hi;
        }
        if (tid < 32) { Lk[m0 + tid] = lkacc; Lk[256 + m0 + tid] = lkacc; }
    }

    // ---- slots 1..127: chunk s-1 rows; after accumulating, carry -> slot s+1
    for (int s = 1; s < 128; s++) {
        const size_t t0 = LCOND + (size_t)(s - 1) * LCH;
        __syncthreads();
        for (int idx = tid; idx < LCH * 32; idx += 256) {
            int row = idx >> 5, mc = idx & 31;
            kp_s[idx] = fmaf(Eb[(t0 + row) * 256 + m0 + mc], rs, rk);
        }
        for (int idx = tid; idx < LCH * 64; idx += 256)
            v_s[idx] = vb[t0 * 64 + idx];
        __syncthreads();
#pragma unroll 5
        for (int row = 0; row < LCH; row++) {
            float vsc = v_s[row * 64 + e];
            unsigned long long vv; PACK2(vv, vsc, vsc);
            const float* kr = &kp_s[row * 32 + mg2 * 8];
            ulonglong2 k01 = *(const ulonglong2*)&kr[0];
            ulonglong2 k23 = *(const ulonglong2*)&kr[4];
            FMA2(acc[0], k01.x, vv); FMA2(acc[1], k01.y, vv);
            FMA2(acc[2], k23.x, vv); FMA2(acc[3], k23.y, vv);
        }
        if (tid < 32) {
#pragma unroll 6
            for (int row = 0; row < LCH; row++) lkacc += kp_s[row * 32 + tid];
        }
        size_t ob = (size_t)(s + 1) * 16384 + (size_t)(m0 + mg2 * 8) * 64 + e;
#pragma unroll
        for (int p = 0; p < 4; p++) {
            float lo, hi; UNPACK2(lo, hi, acc[p]);
            Lc[ob + (size_t)(2 * p    ) * 64] = lo;
            Lc[ob + (size_t)(2 * p + 1) * 64] = hi;
        }
        if (tid < 32) Lk[(size_t)(s + 1) * 256 + m0 + tid] = lkacc;
    }
}

// ---------------- conditioning-prefix output ---------------------------------
__global__ __launch_bounds__(128) void cond_out_kernel(float* __restrict__ out) {
    __shared__ float sden[4];
    const int tid = threadIdx.x;
    const int rl = tid >> 6, e = tid & 63;
    const int lane = tid & 31, wid = tid >> 5;
    const int bh = blockIdx.y;
    const int row = blockIdx.x * 2 + rl;
    const float* qrow = g_QP + ((size_t)bh * NSEQ + row) * 256;
    const float* lk0  = g_Lk   + (size_t)bh * NSLOT * 256;
    const float* ctx0 = g_Lctx + (size_t)bh * NSLOT * 16384;

    float p = 0.f;
    for (int m = e; m < 256; m += 64) p += qrow[m] * lk0[m];
    for (int off = 16; off; off >>= 1) p += __shfl_xor_sync(0xffffffffu, p, off);
    if (lane == 0) sden[wid] = p;
    __syncthreads();
    float den = sden[rl * 2] + sden[rl * 2 + 1];

    float acc = 0.f;
    for (int m4 = 0; m4 < 64; m4++) {
        float4 q4 = *(const float4*)&qrow[m4 * 4];
        acc += q4.x * ctx0[(m4 * 4 + 0) * 64 + e] + q4.y * ctx0[(m4 * 4 + 1) * 64 + e]
             + q4.z * ctx0[(m4 * 4 + 2) * 64 + e] + q4.w * ctx0[(m4 * 4 + 3) * 64 + e];
    }
    out[((size_t)bh * NSEQ + row) * 64 + e] = acc / den;
}

// ---------------- causal chunk output (kp = fma(E, rs, rk)) ------------------
#define QPAD 132
#define KPAD 133

__global__ __launch_bounds__(256) void causal_out_kernel(const float* __restrict__ v,
                                                         float* __restrict__ out) {
    __shared__ float q_s[LCH * QPAD];   // 15.84 KB
    __shared__ float k_s[LCH * KPAD];   // 15.96 KB
    __shared__ float v_s[LCH * 64];     // 7.5 KB
    __shared__ float A[32 * 32];
    __shared__ float ck[256];
    __shared__ float dinv[32];

    const int tid = threadIdx.x, lane = tid & 31, w = tid >> 5;
    const int ci = blockIdx.x, bh = blockIdx.y;
    const int t0 = LCOND + ci * LCH;
    const int slot = ci + 1;
    const float gmax = fuord(g_kmax);
    const float rs = RATIO * __expf(-gmax);
    const float rk = RATIO * EPSK;

    const float* qb = g_QP + ((size_t)bh * NSEQ + t0) * 256;
    const float* kb = g_KE + ((size_t)bh * NSEQ + t0) * 256;
    const float* vb = v    + ((size_t)bh * NSEQ + t0) * 64;
    const float* ctxc = g_Lctx + ((size_t)bh * NSLOT + slot) * 16384;

    for (int idx = tid; idx < LCH * 64; idx += 256) v_s[idx] = vb[idx];
    ck[tid] = g_Lk[((size_t)bh * NSLOT + slot) * 256 + tid];

    float a0 = 0.f, a1 = 0.f, a2 = 0.f, a3 = 0.f;
    float pden[4] = {0.f, 0.f, 0.f, 0.f};
    const int g = tid >> 6, e = tid & 63;
    float acc[8];
#pragma unroll
    for (int r = 0; r < 8; r++) acc[r] = 0.f;

    const int klane = (lane < LCH) ? lane : (LCH - 1);

    for (int mt = 0; mt < 2; mt++) {
        const int m0 = mt * 128;
        __syncthreads();
        for (int idx = tid; idx < LCH * 128; idx += 256) {
            int i = idx >> 7, ml = idx & 127;
            q_s[i * QPAD + ml] = qb[i * 256 + m0 + ml];
            k_s[i * KPAD + ml] = fmaf(kb[i * 256 + m0 + ml], rs, rk);
        }
        __syncthreads();

        {
            const float* krow = &k_s[klane * KPAD];
            const int iA = w, iB = w + 8, iC = w + 16, iD = (w + 24 < LCH) ? w + 24 : 0;
#pragma unroll 8
            for (int m4 = 0; m4 < 32; m4++) {
                float k0 = krow[m4 * 4 + 0], k1 = krow[m4 * 4 + 1];
                float k2 = krow[m4 * 4 + 2], k3 = krow[m4 * 4 + 3];
                float4 qA = *(const float4*)&q_s[iA * QPAD + m4 * 4];
                float4 qB = *(const float4*)&q_s[iB * QPAD + m4 * 4];
                float4 qC = *(const float4*)&q_s[iC * QPAD + m4 * 4];
                float4 qD = *(const float4*)&q_s[iD * QPAD + m4 * 4];
                a0 += qA.x * k0 + qA.y * k1 + qA.z * k2 + qA.w * k3;
                a1 += qB.x * k0 + qB.y * k1 + qB.z * k2 + qB.w * k3;
                a2 += qC.x * k0 + qC.y * k1 + qC.z * k2 + qC.w * k3;
                a3 += qD.x * k0 + qD.y * k1 + qD.z * k2 + qD.w * k3;
            }
        }

#pragma unroll
        for (int r = 0; r < 4; r++) {
            int i = w + 8 * r;
            if (i < LCH) {
                float p = 0.f;
                for (int ml = lane; ml < 128; ml += 32)
                    p += q_s[i * QPAD + ml] * (ck[m0 + ml] + EPSC);
                pden[r] += p;
            }
        }

        for (int m4 = 0; m4 < 32; m4++) {
            float c0 = ctxc[(m0 + m4 * 4 + 0) * 64 + e];
            float c1 = ctxc[(m0 + m4 * 4 + 1) * 64 + e];
            float c2 = ctxc[(m0 + m4 * 4 + 2) * 64 + e];
            float c3 = ctxc[(m0 + m4 * 4 + 3) * 64 + e];
#pragma unroll
            for (int r = 0; r < 8; r++) {
                int i = g + 4 * r;
                if (i < LCH) {
                    float4 q4 = *(const float4*)&q_s[i * QPAD + m4 * 4];
                    acc[r] += q4.x * c0 + q4.y * c1 + q4.z * c2 + q4.w * c3;
                }
            }
        }
    }

    if (lane < LCH) {
        A[(w     ) * 32 + lane] = a0;
        A[(w +  8) * 32 + lane] = a1;
        A[(w + 16) * 32 + lane] = a2;
        if (w + 24 < LCH) A[(w + 24) * 32 + lane] = a3;
    }
    __syncthreads();

#pragma unroll
    for (int r = 0; r < 4; r++) {
        int i = w + 8 * r;
        if (i < LCH) {
            float p = pden[r];
            if (lane <= i) p += A[i * 32 + lane];
            for (int off = 16; off; off >>= 1) p += __shfl_xor_sync(0xffffffffu, p, off);
            if (lane == 0) dinv[i] = 1.f / p;
        }
    }
    __syncthreads();

#pragma unroll
    for (int r = 0; r < 8; r++) {
        int i = g + 4 * r;
        if (i >= LCH) continue;
        float o = acc[r];
        for (int j = 0; j <= i; j++) o += A[i * 32 + j] * v_s[j * 64 + e];
        out[((size_t)bh * NSEQ + t0 + i) * 64 + e] = o * dinv[i];
    }
}

// ---------------- launch ------------------------------------------------------
extern "C" void kernel_launch(void* const* d_in, const int* in_sizes, int n_in,
                              void* d_out, int out_size) {
    (void)in_sizes; (void)n_in; (void)out_size;
    const float* q    = (const float*)d_in[0];
    const float* k    = (const float*)d_in[1];
    const float* v    = (const float*)d_in[2];
    const float* proj = (const float*)d_in[3];
    float* out = (float*)d_out;

    init_kernel<<<1, 1>>>();
    feat_kernel<false><<<4096, 256>>>(k, proj);
    feat_kernel<true> <<<4096, 256>>>(q, proj);
    fused_sums_kernel <<<dim3(8, BHN), 256>>>(v);
    cond_out_kernel   <<<dim3(128, BHN), 128>>>(out);
    causal_out_kernel <<<dim3(NCHUNK, BHN), 256>>>(v, out);
}

// round 12
// speedup vs baseline: 1.2631x; 1.2631x over previous
#include <cuda_runtime.h>
#include <math.h>

// Problem constants (b=2,h=8,n=4096,d=64,m=256)
#define BHN   16
#define NSEQ  4096
#define DDIM  64
#define MDIM  256
#define LCOND 256
#define NCHUNK 128
#define LCH   30
#define EDIM  64
#define NSLOT 129         // cond(0) + 128 causal chunks

#define NORMALIZER 0.35355339059327373f  // 64^-0.25
#define DIAGC      0.0625f               // 0.5 * normalizer^2
#define RATIO      0.0625f               // 256^-0.5
#define EPSK       1e-4f
#define EPSC       1e-6f

// packed f32x2 helpers (Blackwell FFMA2 path)
#define FMA2(acc, a, b)  asm("fma.rn.f32x2 %0, %1, %2, %0;" : "+l"(acc) : "l"(a), "l"(b))
#define PACK2(d, x, y)   asm("mov.b64 %0, {%1, %2};" : "=l"(d) : "f"(x), "f"(y))
#define UNPACK2(x, y, s) asm("mov.b64 {%0, %1}, %2;" : "=f"(x), "=f"(y) : "l"(s))

// ---------------- scratch (static device globals; allocation-free) -----------
__device__ float g_QP[(size_t)BHN * NSEQ * MDIM];            // 64 MB  qp (final)
__device__ float g_KE[(size_t)BHN * NSEQ * MDIM];            // 64 MB  E = exp(dash-diag)
__device__ unsigned g_kmax;
__device__ float g_Lk  [(size_t)BHN * NSLOT * MDIM];
__device__ float g_Lctx[(size_t)BHN * NSLOT * MDIM * EDIM];  // 135 MB

__device__ __forceinline__ unsigned ford(float f) {
    unsigned u = __float_as_uint(f);
    return (u & 0x80000000u) ? ~u : (u | 0x80000000u);
}
__device__ __forceinline__ float fuord(unsigned u) {
    return (u & 0x80000000u) ? __uint_as_float(u ^ 0x80000000u)
                             : __uint_as_float(~u);
}

__global__ void init_kernel() { g_kmax = 0u; }

// ---------------- feature map (merged K/Q):  dash = norm * (X @ projT) -------
// grid (4096, 2): blockIdx.y == 0 -> K path, 1 -> Q path.
__global__ __launch_bounds__(256) void feat_kernel(const float* __restrict__ q,
                                                   const float* __restrict__ k,
                                                   const float* __restrict__ proj) {
    __shared__ float qt[64 * 20];       // 5.1 KB transposed tile
    __shared__ float red[8 * 16];
    __shared__ float diag_s[16];
    __shared__ float rmax_s[16];

    const int tid  = threadIdx.x;
    const int lane = tid & 31, wid = tid >> 5;
    const bool is_q = (blockIdx.y != 0);
    const float* data = is_q ? q : k;
    const size_t row0 = (size_t)blockIdx.x * 16;

    float4 pr[16];                       // this thread's proj row (64 floats)
#pragma unroll
    for (int i = 0; i < 16; i++) pr[i] = *(const float4*)&proj[tid * 64 + i * 4];

    for (int idx = tid; idx < 16 * 64; idx += 256) {
        int r = idx >> 6, d = idx & 63;
        qt[d * 20 + r] = data[(row0 + r) * 64 + d];
    }
    __syncthreads();

    if (tid < 16) {
        float s = 0.f;
        for (int d = 0; d < 64; d++) { float x = qt[d * 20 + tid]; s += x * x; }
        diag_s[tid] = s * DIAGC;
    }
    __syncthreads();

    unsigned long long accp[8];
#pragma unroll
    for (int t = 0; t < 8; t++) accp[t] = 0ull;

#pragma unroll
    for (int d = 0; d < 64; d++) {
        float pd = ((d & 3) == 0) ? pr[d >> 2].x :
                   ((d & 3) == 1) ? pr[d >> 2].y :
                   ((d & 3) == 2) ? pr[d >> 2].z : pr[d >> 2].w;
        unsigned long long pp; PACK2(pp, pd, pd);
        ulonglong2 q0 = *(const ulonglong2*)&qt[d * 20 + 0];    // rows (0,1),(2,3)
        ulonglong2 q1 = *(const ulonglong2*)&qt[d * 20 + 4];
        ulonglong2 q2 = *(const ulonglong2*)&qt[d * 20 + 8];
        ulonglong2 q3 = *(const ulonglong2*)&qt[d * 20 + 12];
        FMA2(accp[0], q0.x, pp); FMA2(accp[1], q0.y, pp);
        FMA2(accp[2], q1.x, pp); FMA2(accp[3], q1.y, pp);
        FMA2(accp[4], q2.x, pp); FMA2(accp[5], q2.y, pp);
        FMA2(accp[6], q3.x, pp); FMA2(accp[7], q3.y, pp);
    }

    float dash[16];
#pragma unroll
    for (int t = 0; t < 8; t++) UNPACK2(dash[2 * t], dash[2 * t + 1], accp[t]);
#pragma unroll
    for (int r = 0; r < 16; r++) dash[r] *= NORMALIZER;

    if (is_q) {
#pragma unroll
        for (int r = 0; r < 16; r++) {
            float v = dash[r];
            for (int off = 16; off; off >>= 1)
                v = fmaxf(v, __shfl_xor_sync(0xffffffffu, v, off));
            if (lane == 0) red[wid * 16 + r] = v;
        }
        __syncthreads();
        if (tid < 16) {
            float m = red[tid];
            for (int w = 1; w < 8; w++) m = fmaxf(m, red[w * 16 + tid]);
            rmax_s[tid] = m;
        }
        __syncthreads();
#pragma unroll
        for (int r = 0; r < 16; r++)
            g_QP[(row0 + r) * 256 + tid] =
                RATIO * (__expf(dash[r] - diag_s[r] - rmax_s[r]) + EPSK);
    } else {
        float bm = dash[0];
#pragma unroll
        for (int r = 1; r < 16; r++) bm = fmaxf(bm, dash[r]);
        for (int off = 16; off; off >>= 1)
            bm = fmaxf(bm, __shfl_xor_sync(0xffffffffu, bm, off));
        if (lane == 0) red[wid] = bm;
        __syncthreads();
        if (tid == 0) {
            float m = red[0];
            for (int w = 1; w < 8; w++) m = fmaxf(m, red[w]);
            atomicMax(&g_kmax, ford(m));
        }
#pragma unroll
        for (int r = 0; r < 16; r++)
            g_KE[(row0 + r) * 256 + tid] = __expf(dash[r] - diag_s[r]);   // E
    }
}

// ---------------- per-chunk local sums v4 (as R10) ---------------------------
__device__ __forceinline__ void cs4_mac(const float* __restrict__ kp_s,
                                        const float* __restrict__ v_s,
                                        int tl, int e, int mg,
                                        unsigned long long* acc) {
#pragma unroll 5
    for (int tt = 0; tt < tl; tt++) {
        float vsc = v_s[tt * 64 + e];                   // lane stride-1
        unsigned long long vv; PACK2(vv, vsc, vsc);
        const float* kr = &kp_s[tt * 256 + mg * 32];    // warp-uniform -> broadcast
#pragma unroll
        for (int q = 0; q < 8; q++) {
            ulonglong2 kp2 = *(const ulonglong2*)&kr[q * 4];   // 2 m-pairs
            FMA2(acc[q * 2 + 0], kp2.x, vv);
            FMA2(acc[q * 2 + 1], kp2.y, vv);
        }
    }
}

__global__ __launch_bounds__(512, 2) void chunk_sums_kernel(const float* __restrict__ v) {
    __shared__ float kp_s[32 * 256];    // 32 KB
    __shared__ float v_s[32 * 64];      // 8 KB
    const int tid = threadIdx.x;
    const int e = tid & 63, mg = tid >> 6;       // mg uniform per warp
    const int slot = blockIdx.x, bh = blockIdx.y;
    const int t0  = slot ? (LCOND + (slot - 1) * LCH) : 0;
    const float gmax = fuord(g_kmax);
    const float rs = RATIO * __expf(-gmax);
    const float rk = RATIO * EPSK;

    unsigned long long acc[16];
#pragma unroll
    for (int c = 0; c < 16; c++) acc[c] = 0ull;
    float sk = 0.f;                               // threads < 256: m = tid

    const float* Eb = g_KE + ((size_t)bh * NSEQ + t0) * 256;
    const float* vb = v    + ((size_t)bh * NSEQ + t0) * 64;

    if (slot == 0) {
        for (int base = 0; base < LCOND; base += 32) {
            __syncthreads();
            for (int idx = tid; idx < 32 * 256; idx += 512)
                kp_s[idx] = fmaf(Eb[(size_t)base * 256 + idx], rs, rk);
            for (int idx = tid; idx < 32 * 64; idx += 512)
                v_s[idx] = vb[(size_t)base * 64 + idx];
            __syncthreads();
            cs4_mac(kp_s, v_s, 32, e, mg, acc);
            if (tid < 256) {
#pragma unroll 8
                for (int tt = 0; tt < 32; tt++) sk += kp_s[tt * 256 + tid];
            }
        }
    } else {
        for (int idx = tid; idx < LCH * 256; idx += 512)
            kp_s[idx] = fmaf(Eb[idx], rs, rk);
        for (int idx = tid; idx < LCH * 64; idx += 512)
            v_s[idx] = vb[idx];
        __syncthreads();
        cs4_mac(kp_s, v_s, LCH, e, mg, acc);
        if (tid < 256) {
#pragma unroll 6
            for (int tt = 0; tt < LCH; tt++) sk += kp_s[tt * 256 + tid];
        }
    }

    if (tid < 256) g_Lk[((size_t)bh * NSLOT + slot) * 256 + tid] = sk;

    // coalesced stores: per m, lanes write consecutive e
    size_t ob = (((size_t)bh * NSLOT + slot) * 256 + mg * 32) * 64 + e;
#pragma unroll
    for (int p = 0; p < 16; p++) {
        float lo, hi; UNPACK2(lo, hi, acc[p]);
        g_Lctx[ob + (size_t)(2 * p    ) * 64] = lo;
        g_Lctx[ob + (size_t)(2 * p + 1) * 64] = hi;
    }
}

// ---------------- exclusive prefix over chunks (float4 + MLP=8) --------------
__global__ __launch_bounds__(256) void prefix_kernel() {
    const int g = blockIdx.x * 256 + threadIdx.x;   // 0..4351
    const int bh = blockIdx.y;

    if (g < 256) {
        size_t base = (size_t)bh * NSLOT * 256 + g;
        float acc = g_Lk[base];
#pragma unroll 1
        for (int c0 = 1; c0 < NSLOT; c0 += 8) {
            float t[8];
#pragma unroll
            for (int u = 0; u < 8; u++)
                t[u] = g_Lk[base + (size_t)(c0 + u) * 256];
#pragma unroll
            for (int u = 0; u < 8; u++) {
                float nxt = t[u];
                g_Lk[base + (size_t)(c0 + u) * 256] = acc;
                acc += nxt;
            }
        }
    } else {
        size_t base = (size_t)bh * NSLOT * 16384 + (size_t)(g - 256) * 4;
        float4 acc = *(float4*)&g_Lctx[base];
#pragma unroll 1
        for (int c0 = 1; c0 < NSLOT; c0 += 8) {
            float4 t[8];
#pragma unroll
            for (int u = 0; u < 8; u++)
                t[u] = *(float4*)&g_Lctx[base + (size_t)(c0 + u) * 16384];
#pragma unroll
            for (int u = 0; u < 8; u++) {
                float4 nxt = t[u];
                *(float4*)&g_Lctx[base + (size_t)(c0 + u) * 16384] = acc;
                acc.x += nxt.x; acc.y += nxt.y; acc.z += nxt.z; acc.w += nxt.w;
            }
        }
    }
}

// ---------------- conditioning-prefix output ---------------------------------
__global__ __launch_bounds__(128) void cond_out_kernel(float* __restrict__ out) {
    __shared__ float sden[4];
    const int tid = threadIdx.x;
    const int rl = tid >> 6, e = tid & 63;
    const int lane = tid & 31, wid = tid >> 5;
    const int bh = blockIdx.y;
    const int row = blockIdx.x * 2 + rl;
    const float* qrow = g_QP + ((size_t)bh * NSEQ + row) * 256;
    const float* lk0  = g_Lk   + (size_t)bh * NSLOT * 256;
    const float* ctx0 = g_Lctx + (size_t)bh * NSLOT * 16384;

    float p = 0.f;
    for (int m = e; m < 256; m += 64) p += qrow[m] * lk0[m];
    for (int off = 16; off; off >>= 1) p += __shfl_xor_sync(0xffffffffu, p, off);
    if (lane == 0) sden[wid] = p;
    __syncthreads();
    float den = sden[rl * 2] + sden[rl * 2 + 1];

    float acc = 0.f;
    for (int m4 = 0; m4 < 64; m4++) {
        float4 q4 = *(const float4*)&qrow[m4 * 4];
        acc += q4.x * ctx0[(m4 * 4 + 0) * 64 + e] + q4.y * ctx0[(m4 * 4 + 1) * 64 + e]
             + q4.z * ctx0[(m4 * 4 + 2) * 64 + e] + q4.w * ctx0[(m4 * 4 + 3) * 64 + e];
    }
    out[((size_t)bh * NSEQ + row) * 64 + e] = acc / den;
}

// ---------------- causal chunk output (kp = fma(E, rs, rk)) ------------------
#define QPAD 132
#define KPAD 133

__global__ __launch_bounds__(256) void causal_out_kernel(const float* __restrict__ v,
                                                         float* __restrict__ out) {
    __shared__ float q_s[LCH * QPAD];   // 15.84 KB
    __shared__ float k_s[LCH * KPAD];   // 15.96 KB
    __shared__ float v_s[LCH * 64];     // 7.5 KB
    __shared__ float A[32 * 32];
    __shared__ float ck[256];
    __shared__ float dinv[32];

    const int tid = threadIdx.x, lane = tid & 31, w = tid >> 5;
    const int ci = blockIdx.x, bh = blockIdx.y;
    const int t0 = LCOND + ci * LCH;
    const int slot = ci + 1;
    const float gmax = fuord(g_kmax);
    const float rs = RATIO * __expf(-gmax);
    const float rk = RATIO * EPSK;

    const float* qb = g_QP + ((size_t)bh * NSEQ + t0) * 256;
    const float* kb = g_KE + ((size_t)bh * NSEQ + t0) * 256;
    const float* vb = v    + ((size_t)bh * NSEQ + t0) * 64;
    const float* ctxc = g_Lctx + ((size_t)bh * NSLOT + slot) * 16384;

    for (int idx = tid; idx < LCH * 64; idx += 256) v_s[idx] = vb[idx];
    ck[tid] = g_Lk[((size_t)bh * NSLOT + slot) * 256 + tid];

    float a0 = 0.f, a1 = 0.f, a2 = 0.f, a3 = 0.f;
    float pden[4] = {0.f, 0.f, 0.f, 0.f};
    const int g = tid >> 6, e = tid & 63;
    float acc[8];
#pragma unroll
    for (int r = 0; r < 8; r++) acc[r] = 0.f;

    const int klane = (lane < LCH) ? lane : (LCH - 1);

    for (int mt = 0; mt < 2; mt++) {
        const int m0 = mt * 128;
        __syncthreads();
        for (int idx = tid; idx < LCH * 128; idx += 256) {
            int i = idx >> 7, ml = idx & 127;
            q_s[i * QPAD + ml] = qb[i * 256 + m0 + ml];
            k_s[i * KPAD + ml] = fmaf(kb[i * 256 + m0 + ml], rs, rk);
        }
        __syncthreads();

        {
            const float* krow = &k_s[klane * KPAD];
            const int iA = w, iB = w + 8, iC = w + 16, iD = (w + 24 < LCH) ? w + 24 : 0;
#pragma unroll 8
            for (int m4 = 0; m4 < 32; m4++) {
                float k0 = krow[m4 * 4 + 0], k1 = krow[m4 * 4 + 1];
                float k2 = krow[m4 * 4 + 2], k3 = krow[m4 * 4 + 3];
                float4 qA = *(const float4*)&q_s[iA * QPAD + m4 * 4];
                float4 qB = *(const float4*)&q_s[iB * QPAD + m4 * 4];
                float4 qC = *(const float4*)&q_s[iC * QPAD + m4 * 4];
                float4 qD = *(const float4*)&q_s[iD * QPAD + m4 * 4];
                a0 += qA.x * k0 + qA.y * k1 + qA.z * k2 + qA.w * k3;
                a1 += qB.x * k0 + qB.y * k1 + qB.z * k2 + qB.w * k3;
                a2 += qC.x * k0 + qC.y * k1 + qC.z * k2 + qC.w * k3;
                a3 += qD.x * k0 + qD.y * k1 + qD.z * k2 + qD.w * k3;
            }
        }

#pragma unroll
        for (int r = 0; r < 4; r++) {
            int i = w + 8 * r;
            if (i < LCH) {
                float p = 0.f;
                for (int ml = lane; ml < 128; ml += 32)
                    p += q_s[i * QPAD + ml] * (ck[m0 + ml] + EPSC);
                pden[r] += p;
            }
        }

        for (int m4 = 0; m4 < 32; m4++) {
            float c0 = ctxc[(m0 + m4 * 4 + 0) * 64 + e];
            float c1 = ctxc[(m0 + m4 * 4 + 1) * 64 + e];
            float c2 = ctxc[(m0 + m4 * 4 + 2) * 64 + e];
            float c3 = ctxc[(m0 + m4 * 4 + 3) * 64 + e];
#pragma unroll
            for (int r = 0; r < 8; r++) {
                int i = g + 4 * r;
                if (i < LCH) {
                    float4 q4 = *(const float4*)&q_s[i * QPAD + m4 * 4];
                    acc[r] += q4.x * c0 + q4.y * c1 + q4.z * c2 + q4.w * c3;
                }
            }
        }
    }

    if (lane < LCH) {
        A[(w     ) * 32 + lane] = a0;
        A[(w +  8) * 32 + lane] = a1;
        A[(w + 16) * 32 + lane] = a2;
        if (w + 24 < LCH) A[(w + 24) * 32 + lane] = a3;
    }
    __syncthreads();

#pragma unroll
    for (int r = 0; r < 4; r++) {
        int i = w + 8 * r;
        if (i < LCH) {
            float p = pden[r];
            if (lane <= i) p += A[i * 32 + lane];
            for (int off = 16; off; off >>= 1) p += __shfl_xor_sync(0xffffffffu, p, off);
            if (lane == 0) dinv[i] = 1.f / p;
        }
    }
    __syncthreads();

#pragma unroll
    for (int r = 0; r < 8; r++) {
        int i = g + 4 * r;
        if (i >= LCH) continue;
        float o = acc[r];
        for (int j = 0; j <= i; j++) o += A[i * 32 + j] * v_s[j * 64 + e];
        out[((size_t)bh * NSEQ + t0 + i) * 64 + e] = o * dinv[i];
    }
}

// ---------------- launch ------------------------------------------------------
extern "C" void kernel_launch(void* const* d_in, const int* in_sizes, int n_in,
                              void* d_out, int out_size) {
    (void)in_sizes; (void)n_in; (void)out_size;
    const float* q    = (const float*)d_in[0];
    const float* k    = (const float*)d_in[1];
    const float* v    = (const float*)d_in[2];
    const float* proj = (const float*)d_in[3];
    float* out = (float*)d_out;

    init_kernel<<<1, 1>>>();
    feat_kernel       <<<dim3(4096, 2), 256>>>(q, k, proj);
    chunk_sums_kernel <<<dim3(NSLOT, BHN), 512>>>(v);
    prefix_kernel     <<<dim3(17, BHN), 256>>>();
    cond_out_kernel   <<<dim3(128, BHN), 128>>>(out);
    causal_out_kernel <<<dim3(NCHUNK, BHN), 256>>>(v, out);
}

// round 14
// speedup vs baseline: 1.3511x; 1.0697x over previous
#include <cuda_runtime.h>
#include <math.h>

// Problem constants (b=2,h=8,n=4096,d=64,m=256)
#define BHN   16
#define NSEQ  4096
#define DDIM  64
#define MDIM  256
#define LCOND 256
#define NCHUNK 128
#define LCH   30
#define EDIM  64
#define NSLOT 129         // cond(0) + 128 causal chunks

#define NORMALIZER 0.35355339059327373f  // 64^-0.25
#define DIAGC      0.0625f               // 0.5 * normalizer^2
#define RATIO      0.0625f               // 256^-0.5
#define EPSK       1e-4f
#define EPSC       1e-6f

// packed f32x2 helpers (Blackwell FFMA2 path)
#define FMA2(acc, a, b)  asm("fma.rn.f32x2 %0, %1, %2, %0;" : "+l"(acc) : "l"(a), "l"(b))
#define PACK2(d, x, y)   asm("mov.b64 %0, {%1, %2};" : "=l"(d) : "f"(x), "f"(y))
#define UNPACK2(x, y, s) asm("mov.b64 {%0, %1}, %2;" : "=f"(x), "=f"(y) : "l"(s))

// ---------------- scratch (static device globals; allocation-free) -----------
__device__ float g_QP[(size_t)BHN * NSEQ * MDIM];            // 64 MB  qp (final)
__device__ float g_KE[(size_t)BHN * NSEQ * MDIM];            // 64 MB  E = exp(dash-diag)
__device__ unsigned g_kmax;
__device__ float g_Lk  [(size_t)BHN * NSLOT * MDIM];
__device__ float g_Lctx[(size_t)BHN * NSLOT * MDIM * EDIM];  // 135 MB
__device__ float g_SegLk [(size_t)BHN * 256 * 4];            // segment sums (Lk)
__device__ float g_SegCtx[(size_t)BHN * 4096 * 4 * 4];       // segment sums (ctx, float4)

__device__ __forceinline__ unsigned ford(float f) {
    unsigned u = __float_as_uint(f);
    return (u & 0x80000000u) ? ~u : (u | 0x80000000u);
}
__device__ __forceinline__ float fuord(unsigned u) {
    return (u & 0x80000000u) ? __uint_as_float(u ^ 0x80000000u)
                             : __uint_as_float(~u);
}

__global__ void init_kernel() { g_kmax = 0u; }

// ---------------- feature map (merged K/Q):  dash = norm * (X @ projT) -------
__global__ __launch_bounds__(256) void feat_kernel(const float* __restrict__ q,
                                                   const float* __restrict__ k,
                                                   const float* __restrict__ proj) {
    __shared__ float qt[64 * 20];       // 5.1 KB transposed tile
    __shared__ float red[8 * 16];
    __shared__ float diag_s[16];
    __shared__ float rmax_s[16];

    const int tid  = threadIdx.x;
    const int lane = tid & 31, wid = tid >> 5;
    const bool is_q = (blockIdx.y != 0);
    const float* data = is_q ? q : k;
    const size_t row0 = (size_t)blockIdx.x * 16;

    float4 pr[16];
#pragma unroll
    for (int i = 0; i < 16; i++) pr[i] = *(const float4*)&proj[tid * 64 + i * 4];

    for (int idx = tid; idx < 16 * 64; idx += 256) {
        int r = idx >> 6, d = idx & 63;
        qt[d * 20 + r] = data[(row0 + r) * 64 + d];
    }
    __syncthreads();

    if (tid < 16) {
        float s = 0.f;
        for (int d = 0; d < 64; d++) { float x = qt[d * 20 + tid]; s += x * x; }
        diag_s[tid] = s * DIAGC;
    }
    __syncthreads();

    unsigned long long accp[8];
#pragma unroll
    for (int t = 0; t < 8; t++) accp[t] = 0ull;

#pragma unroll
    for (int d = 0; d < 64; d++) {
        float pd = ((d & 3) == 0) ? pr[d >> 2].x :
                   ((d & 3) == 1) ? pr[d >> 2].y :
                   ((d & 3) == 2) ? pr[d >> 2].z : pr[d >> 2].w;
        unsigned long long pp; PACK2(pp, pd, pd);
        ulonglong2 q0 = *(const ulonglong2*)&qt[d * 20 + 0];
        ulonglong2 q1 = *(const ulonglong2*)&qt[d * 20 + 4];
        ulonglong2 q2 = *(const ulonglong2*)&qt[d * 20 + 8];
        ulonglong2 q3 = *(const ulonglong2*)&qt[d * 20 + 12];
        FMA2(accp[0], q0.x, pp); FMA2(accp[1], q0.y, pp);
        FMA2(accp[2], q1.x, pp); FMA2(accp[3], q1.y, pp);
        FMA2(accp[4], q2.x, pp); FMA2(accp[5], q2.y, pp);
        FMA2(accp[6], q3.x, pp); FMA2(accp[7], q3.y, pp);
    }

    float dash[16];
#pragma unroll
    for (int t = 0; t < 8; t++) UNPACK2(dash[2 * t], dash[2 * t + 1], accp[t]);
#pragma unroll
    for (int r = 0; r < 16; r++) dash[r] *= NORMALIZER;

    if (is_q) {
#pragma unroll
        for (int r = 0; r < 16; r++) {
            float v = dash[r];
            for (int off = 16; off; off >>= 1)
                v = fmaxf(v, __shfl_xor_sync(0xffffffffu, v, off));
            if (lane == 0) red[wid * 16 + r] = v;
        }
        __syncthreads();
        if (tid < 16) {
            float m = red[tid];
            for (int w = 1; w < 8; w++) m = fmaxf(m, red[w * 16 + tid]);
            rmax_s[tid] = m;
        }
        __syncthreads();
#pragma unroll
        for (int r = 0; r < 16; r++)
            g_QP[(row0 + r) * 256 + tid] =
                RATIO * (__expf(dash[r] - diag_s[r] - rmax_s[r]) + EPSK);
    } else {
        float bm = dash[0];
#pragma unroll
        for (int r = 1; r < 16; r++) bm = fmaxf(bm, dash[r]);
        for (int off = 16; off; off >>= 1)
            bm = fmaxf(bm, __shfl_xor_sync(0xffffffffu, bm, off));
        if (lane == 0) red[wid] = bm;
        __syncthreads();
        if (tid == 0) {
            float m = red[0];
            for (int w = 1; w < 8; w++) m = fmaxf(m, red[w]);
            atomicMax(&g_kmax, ford(m));
        }
#pragma unroll
        for (int r = 0; r < 16; r++)
            g_KE[(row0 + r) * 256 + tid] = __expf(dash[r] - diag_s[r]);   // E
    }
}

// ---------------- per-chunk local sums v4 (as R10) ---------------------------
__device__ __forceinline__ void cs4_mac(const float* __restrict__ kp_s,
                                        const float* __restrict__ v_s,
                                        int tl, int e, int mg,
                                        unsigned long long* acc) {
#pragma unroll 5
    for (int tt = 0; tt < tl; tt++) {
        float vsc = v_s[tt * 64 + e];
        unsigned long long vv; PACK2(vv, vsc, vsc);
        const float* kr = &kp_s[tt * 256 + mg * 32];
#pragma unroll
        for (int q = 0; q < 8; q++) {
            ulonglong2 kp2 = *(const ulonglong2*)&kr[q * 4];
            FMA2(acc[q * 2 + 0], kp2.x, vv);
            FMA2(acc[q * 2 + 1], kp2.y, vv);
        }
    }
}

__global__ __launch_bounds__(512, 2) void chunk_sums_kernel(const float* __restrict__ v) {
    __shared__ float kp_s[32 * 256];    // 32 KB
    __shared__ float v_s[32 * 64];      // 8 KB
    const int tid = threadIdx.x;
    const int e = tid & 63, mg = tid >> 6;
    const int slot = blockIdx.x, bh = blockIdx.y;
    const int t0  = slot ? (LCOND + (slot - 1) * LCH) : 0;
    const float gmax = fuord(g_kmax);
    const float rs = RATIO * __expf(-gmax);
    const float rk = RATIO * EPSK;

    unsigned long long acc[16];
#pragma unroll
    for (int c = 0; c < 16; c++) acc[c] = 0ull;
    float sk = 0.f;

    const float* Eb = g_KE + ((size_t)bh * NSEQ + t0) * 256;
    const float* vb = v    + ((size_t)bh * NSEQ + t0) * 64;

    if (slot == 0) {
        for (int base = 0; base < LCOND; base += 32) {
            __syncthreads();
            for (int idx = tid; idx < 32 * 256; idx += 512)
                kp_s[idx] = fmaf(Eb[(size_t)base * 256 + idx], rs, rk);
            for (int idx = tid; idx < 32 * 64; idx += 512)
                v_s[idx] = vb[(size_t)base * 64 + idx];
            __syncthreads();
            cs4_mac(kp_s, v_s, 32, e, mg, acc);
            if (tid < 256) {
#pragma unroll 8
                for (int tt = 0; tt < 32; tt++) sk += kp_s[tt * 256 + tid];
            }
        }
    } else {
        for (int idx = tid; idx < LCH * 256; idx += 512)
            kp_s[idx] = fmaf(Eb[idx], rs, rk);
        for (int idx = tid; idx < LCH * 64; idx += 512)
            v_s[idx] = vb[idx];
        __syncthreads();
        cs4_mac(kp_s, v_s, LCH, e, mg, acc);
        if (tid < 256) {
#pragma unroll 6
            for (int tt = 0; tt < LCH; tt++) sk += kp_s[tt * 256 + tid];
        }
    }

    if (tid < 256) g_Lk[((size_t)bh * NSLOT + slot) * 256 + tid] = sk;

    size_t ob = (((size_t)bh * NSLOT + slot) * 256 + mg * 32) * 64 + e;
#pragma unroll
    for (int p = 0; p < 16; p++) {
        float lo, hi; UNPACK2(lo, hi, acc[p]);
        g_Lctx[ob + (size_t)(2 * p    ) * 64] = lo;
        g_Lctx[ob + (size_t)(2 * p + 1) * 64] = hi;
    }
}

// ---------------- segmented exclusive prefix: pass A (segment sums) ----------
// grid (17, BHN, 4): seg z covers slots [1+32z, 32+32z].
__global__ __launch_bounds__(256) void prefix_a_kernel() {
    const int g = blockIdx.x * 256 + threadIdx.x;   // 0..4351
    const int bh = blockIdx.y, seg = blockIdx.z;
    const int c0 = 1 + seg * 32;

    if (g < 256) {
        size_t base = (size_t)bh * NSLOT * 256 + g;
        float s = 0.f;
#pragma unroll
        for (int cb = 0; cb < 32; cb += 8) {
            float t[8];
#pragma unroll
            for (int u = 0; u < 8; u++)
                t[u] = g_Lk[base + (size_t)(c0 + cb + u) * 256];
#pragma unroll
            for (int u = 0; u < 8; u++) s += t[u];
        }
        g_SegLk[((size_t)bh * 256 + g) * 4 + seg] = s;
    } else {
        size_t base = (size_t)bh * NSLOT * 16384 + (size_t)(g - 256) * 4;
        float4 s = make_float4(0.f, 0.f, 0.f, 0.f);
#pragma unroll
        for (int cb = 0; cb < 32; cb += 8) {
            float4 t[8];
#pragma unroll
            for (int u = 0; u < 8; u++)
                t[u] = *(float4*)&g_Lctx[base + (size_t)(c0 + cb + u) * 16384];
#pragma unroll
            for (int u = 0; u < 8; u++) {
                s.x += t[u].x; s.y += t[u].y; s.z += t[u].z; s.w += t[u].w;
            }
        }
        *(float4*)&g_SegCtx[(((size_t)bh * 4096 + (g - 256)) * 4 + seg) * 4] = s;
    }
}

// ---------------- segmented exclusive prefix: pass B (scan within segment) ---
__global__ __launch_bounds__(256) void prefix_b_kernel() {
    const int g = blockIdx.x * 256 + threadIdx.x;   // 0..4351
    const int bh = blockIdx.y, seg = blockIdx.z;
    const int c0 = 1 + seg * 32;

    if (g < 256) {
        size_t base = (size_t)bh * NSLOT * 256 + g;
        float carry = g_Lk[base];                   // slot 0 (untouched by scan)
        for (int j = 0; j < seg; j++)
            carry += g_SegLk[((size_t)bh * 256 + g) * 4 + j];
#pragma unroll
        for (int cb = 0; cb < 32; cb += 8) {
            float t[8];
#pragma unroll
            for (int u = 0; u < 8; u++)
                t[u] = g_Lk[base + (size_t)(c0 + cb + u) * 256];
#pragma unroll
            for (int u = 0; u < 8; u++) {
                float nxt = t[u];
                g_Lk[base + (size_t)(c0 + cb + u) * 256] = carry;
                carry += nxt;
            }
        }
    } else {
        size_t base = (size_t)bh * NSLOT * 16384 + (size_t)(g - 256) * 4;
        float4 carry = *(float4*)&g_Lctx[base];     // slot 0
        for (int j = 0; j < seg; j++) {
            float4 s = *(float4*)&g_SegCtx[(((size_t)bh * 4096 + (g - 256)) * 4 + j) * 4];
            carry.x += s.x; carry.y += s.y; carry.z += s.z; carry.w += s.w;
        }
#pragma unroll
        for (int cb = 0; cb < 32; cb += 8) {
            float4 t[8];
#pragma unroll
            for (int u = 0; u < 8; u++)
                t[u] = *(float4*)&g_Lctx[base + (size_t)(c0 + cb + u) * 16384];
#pragma unroll
            for (int u = 0; u < 8; u++) {
                float4 nxt = t[u];
                *(float4*)&g_Lctx[base + (size_t)(c0 + cb + u) * 16384] = carry;
                carry.x += nxt.x; carry.y += nxt.y; carry.z += nxt.z; carry.w += nxt.w;
            }
        }
    }
}

// ---------------- conditioning-prefix output ---------------------------------
__global__ __launch_bounds__(128) void cond_out_kernel(float* __restrict__ out) {
    __shared__ float sden[4];
    const int tid = threadIdx.x;
    const int rl = tid >> 6, e = tid & 63;
    const int lane = tid & 31, wid = tid >> 5;
    const int bh = blockIdx.y;
    const int row = blockIdx.x * 2 + rl;
    const float* qrow = g_QP + ((size_t)bh * NSEQ + row) * 256;
    const float* lk0  = g_Lk   + (size_t)bh * NSLOT * 256;
    const float* ctx0 = g_Lctx + (size_t)bh * NSLOT * 16384;

    float p = 0.f;
    for (int m = e; m < 256; m += 64) p += qrow[m] * lk0[m];
    for (int off = 16; off; off >>= 1) p += __shfl_xor_sync(0xffffffffu, p, off);
    if (lane == 0) sden[wid] = p;
    __syncthreads();
    float den = sden[rl * 2] + sden[rl * 2 + 1];

    float acc = 0.f;
    for (int m4 = 0; m4 < 64; m4++) {
        float4 q4 = *(const float4*)&qrow[m4 * 4];
        acc += q4.x * ctx0[(m4 * 4 + 0) * 64 + e] + q4.y * ctx0[(m4 * 4 + 1) * 64 + e]
             + q4.z * ctx0[(m4 * 4 + 2) * 64 + e] + q4.w * ctx0[(m4 * 4 + 3) * 64 + e];
    }
    out[((size_t)bh * NSEQ + row) * 64 + e] = acc / den;
}

// ---------------- causal chunk output (kp = fma(E, rs, rk)) ------------------
#define QPAD 132
#define KPAD 133

__global__ __launch_bounds__(256) void causal_out_kernel(const float* __restrict__ v,
                                                         float* __restrict__ out) {
    __shared__ float q_s[LCH * QPAD];   // 15.84 KB
    __shared__ float k_s[LCH * KPAD];   // 15.96 KB
    __shared__ float v_s[LCH * 64];     // 7.5 KB
    __shared__ float A[32 * 32];
    __shared__ float ck[256];
    __shared__ float dinv[32];

    const int tid = threadIdx.x, lane = tid & 31, w = tid >> 5;
    const int ci = blockIdx.x, bh = blockIdx.y;
    const int t0 = LCOND + ci * LCH;
    const int slot = ci + 1;
    const float gmax = fuord(g_kmax);
    const float rs = RATIO * __expf(-gmax);
    const float rk = RATIO * EPSK;

    const float* qb = g_QP + ((size_t)bh * NSEQ + t0) * 256;
    const float* kb = g_KE + ((size_t)bh * NSEQ + t0) * 256;
    const float* vb = v    + ((size_t)bh * NSEQ + t0) * 64;
    const float* ctxc = g_Lctx + ((size_t)bh * NSLOT + slot) * 16384;

    for (int idx = tid; idx < LCH * 64; idx += 256) v_s[idx] = vb[idx];
    ck[tid] = g_Lk[((size_t)bh * NSLOT + slot) * 256 + tid];

    float a0 = 0.f, a1 = 0.f, a2 = 0.f, a3 = 0.f;
    float pden[4] = {0.f, 0.f, 0.f, 0.f};
    const int g = tid >> 6, e = tid & 63;
    float acc[8];
#pragma unroll
    for (int r = 0; r < 8; r++) acc[r] = 0.f;

    const int klane = (lane < LCH) ? lane : (LCH - 1);

    for (int mt = 0; mt < 2; mt++) {
        const int m0 = mt * 128;
        __syncthreads();
        for (int idx = tid; idx < LCH * 128; idx += 256) {
            int i = idx >> 7, ml = idx & 127;
            q_s[i * QPAD + ml] = qb[i * 256 + m0 + ml];
            k_s[i * KPAD + ml] = fmaf(kb[i * 256 + m0 + ml], rs, rk);
        }
        __syncthreads();

        {
            const float* krow = &k_s[klane * KPAD];
            const int iA = w, iB = w + 8, iC = w + 16, iD = (w + 24 < LCH) ? w + 24 : 0;
#pragma unroll 8
            for (int m4 = 0; m4 < 32; m4++) {
                float k0 = krow[m4 * 4 + 0], k1 = krow[m4 * 4 + 1];
                float k2 = krow[m4 * 4 + 2], k3 = krow[m4 * 4 + 3];
                float4 qA = *(const float4*)&q_s[iA * QPAD + m4 * 4];
                float4 qB = *(const float4*)&q_s[iB * QPAD + m4 * 4];
                float4 qC = *(const float4*)&q_s[iC * QPAD + m4 * 4];
                float4 qD = *(const float4*)&q_s[iD * QPAD + m4 * 4];
                a0 += qA.x * k0 + qA.y * k1 + qA.z * k2 + qA.w * k3;
                a1 += qB.x * k0 + qB.y * k1 + qB.z * k2 + qB.w * k3;
                a2 += qC.x * k0 + qC.y * k1 + qC.z * k2 + qC.w * k3;
                a3 += qD.x * k0 + qD.y * k1 + qD.z * k2 + qD.w * k3;
            }
        }

#pragma unroll
        for (int r = 0; r < 4; r++) {
            int i = w + 8 * r;
            if (i < LCH) {
                float p = 0.f;
                for (int ml = lane; ml < 128; ml += 32)
                    p += q_s[i * QPAD + ml] * (ck[m0 + ml] + EPSC);
                pden[r] += p;
            }
        }

        for (int m4 = 0; m4 < 32; m4++) {
            float c0 = ctxc[(m0 + m4 * 4 + 0) * 64 + e];
            float c1 = ctxc[(m0 + m4 * 4 + 1) * 64 + e];
            float c2 = ctxc[(m0 + m4 * 4 + 2) * 64 + e];
            float c3 = ctxc[(m0 + m4 * 4 + 3) * 64 + e];
#pragma unroll
            for (int r = 0; r < 8; r++) {
                int i = g + 4 * r;
                if (i < LCH) {
                    float4 q4 = *(const float4*)&q_s[i * QPAD + m4 * 4];
                    acc[r] += q4.x * c0 + q4.y * c1 + q4.z * c2 + q4.w * c3;
                }
            }
        }
    }

    if (lane < LCH) {
        A[(w     ) * 32 + lane] = a0;
        A[(w +  8) * 32 + lane] = a1;
        A[(w + 16) * 32 + lane] = a2;
        if (w + 24 < LCH) A[(w + 24) * 32 + lane] = a3;
    }
    __syncthreads();

#pragma unroll
    for (int r = 0; r < 4; r++) {
        int i = w + 8 * r;
        if (i < LCH) {
            float p = pden[r];
            if (lane <= i) p += A[i * 32 + lane];
            for (int off = 16; off; off >>= 1) p += __shfl_xor_sync(0xffffffffu, p, off);
            if (lane == 0) dinv[i] = 1.f / p;
        }
    }
    __syncthreads();

#pragma unroll
    for (int r = 0; r < 8; r++) {
        int i = g + 4 * r;
        if (i >= LCH) continue;
        float o = acc[r];
        for (int j = 0; j <= i; j++) o += A[i * 32 + j] * v_s[j * 64 + e];
        out[((size_t)bh * NSEQ + t0 + i) * 64 + e] = o * dinv[i];
    }
}

// ---------------- launch ------------------------------------------------------
extern "C" void kernel_launch(void* const* d_in, const int* in_sizes, int n_in,
                              void* d_out, int out_size) {
    (void)in_sizes; (void)n_in; (void)out_size;
    const float* q    = (const float*)d_in[0];
    const float* k    = (const float*)d_in[1];
    const float* v    = (const float*)d_in[2];
    const float* proj = (const float*)d_in[3];
    float* out = (float*)d_out;

    init_kernel<<<1, 1>>>();
    feat_kernel       <<<dim3(4096, 2), 256>>>(q, k, proj);
    chunk_sums_kernel <<<dim3(NSLOT, BHN), 512>>>(v);
    prefix_a_kernel   <<<dim3(17, BHN, 4), 256>>>();
    prefix_b_kernel   <<<dim3(17, BHN, 4), 256>>>();
    cond_out_kernel   <<<dim3(128, BHN), 128>>>(out);
    causal_out_kernel <<<dim3(NCHUNK, BHN), 256>>>(v, out);
}

// round 17
// speedup vs baseline: 1.3902x; 1.0290x over previous
#include <cuda_runtime.h>
#include <math.h>

// Problem constants (b=2,h=8,n=4096,d=64,m=256)
#define BHN   16
#define NSEQ  4096
#define DDIM  64
#define MDIM  256
#define LCOND 256
#define NCHUNK 128
#define LCH   30
#define EDIM  64
#define NSLOT 129         // cond(0) + 128 causal chunks

#define NORMALIZER 0.35355339059327373f  // 64^-0.25
#define DIAGC      0.0625f               // 0.5 * normalizer^2
#define RATIO      0.0625f               // 256^-0.5
#define EPSK       1e-4f
#define EPSC       1e-6f

// packed f32x2 helpers (Blackwell FFMA2 path)
#define FMA2(acc, a, b)  asm("fma.rn.f32x2 %0, %1, %2, %0;" : "+l"(acc) : "l"(a), "l"(b))
#define PACK2(d, x, y)   asm("mov.b64 %0, {%1, %2};" : "=l"(d) : "f"(x), "f"(y))
#define UNPACK2(x, y, s) asm("mov.b64 {%0, %1}, %2;" : "=f"(x), "=f"(y) : "l"(s))

// ---------------- scratch (static device globals; allocation-free) -----------
__device__ float g_QP[(size_t)BHN * NSEQ * MDIM];            // 64 MB  qp (final)
__device__ float g_KE[(size_t)BHN * NSEQ * MDIM];            // 64 MB  E = exp(dash-diag)
__device__ unsigned g_kmax;
__device__ float g_Lk  [(size_t)BHN * NSLOT * MDIM];
__device__ float g_Lctx[(size_t)BHN * NSLOT * MDIM * EDIM];  // 135 MB
__device__ float g_SegLk [(size_t)BHN * 256 * 4];            // segment sums (Lk)
__device__ float g_SegCtx[(size_t)BHN * 4096 * 4 * 4];       // segment sums (ctx, float4)

__device__ __forceinline__ unsigned ford(float f) {
    unsigned u = __float_as_uint(f);
    return (u & 0x80000000u) ? ~u : (u | 0x80000000u);
}
__device__ __forceinline__ float fuord(unsigned u) {
    return (u & 0x80000000u) ? __uint_as_float(u ^ 0x80000000u)
                             : __uint_as_float(~u);
}

__global__ void init_kernel() { g_kmax = 0u; }

// ---------------- feature map (merged K/Q), chunked proj regs ----------------
// proj loaded in 4 chunks of 16 d's -> fewer live regs; NO forced min-blocks.
__global__ __launch_bounds__(256) void feat_kernel(const float* __restrict__ q,
                                                   const float* __restrict__ k,
                                                   const float* __restrict__ proj) {
    __shared__ float qt[64 * 20];       // 5.1 KB transposed tile
    __shared__ float red[8 * 16];
    __shared__ float diag_s[16];
    __shared__ float rmax_s[16];

    const int tid  = threadIdx.x;
    const int lane = tid & 31, wid = tid >> 5;
    const bool is_q = (blockIdx.y != 0);
    const float* data = is_q ? q : k;
    const size_t row0 = (size_t)blockIdx.x * 16;

    for (int idx = tid; idx < 16 * 64; idx += 256) {
        int r = idx >> 6, d = idx & 63;
        qt[d * 20 + r] = data[(row0 + r) * 64 + d];
    }
    __syncthreads();

    if (tid < 16) {
        float s = 0.f;
        for (int d = 0; d < 64; d++) { float x = qt[d * 20 + tid]; s += x * x; }
        diag_s[tid] = s * DIAGC;
    }
    __syncthreads();

    unsigned long long accp[8];
#pragma unroll
    for (int t = 0; t < 8; t++) accp[t] = 0ull;

#pragma unroll
    for (int dc = 0; dc < 4; dc++) {
        float4 pc[4];
#pragma unroll
        for (int i = 0; i < 4; i++)
            pc[i] = *(const float4*)&proj[tid * 64 + dc * 16 + i * 4];
#pragma unroll
        for (int dd = 0; dd < 16; dd++) {
            const int d = dc * 16 + dd;
            float pd = ((dd & 3) == 0) ? pc[dd >> 2].x :
                       ((dd & 3) == 1) ? pc[dd >> 2].y :
                       ((dd & 3) == 2) ? pc[dd >> 2].z : pc[dd >> 2].w;
            unsigned long long pp; PACK2(pp, pd, pd);
            ulonglong2 q0 = *(const ulonglong2*)&qt[d * 20 + 0];
            ulonglong2 q1 = *(const ulonglong2*)&qt[d * 20 + 4];
            ulonglong2 q2 = *(const ulonglong2*)&qt[d * 20 + 8];
            ulonglong2 q3 = *(const ulonglong2*)&qt[d * 20 + 12];
            FMA2(accp[0], q0.x, pp); FMA2(accp[1], q0.y, pp);
            FMA2(accp[2], q1.x, pp); FMA2(accp[3], q1.y, pp);
            FMA2(accp[4], q2.x, pp); FMA2(accp[5], q2.y, pp);
            FMA2(accp[6], q3.x, pp); FMA2(accp[7], q3.y, pp);
        }
    }

    float dash[16];
#pragma unroll
    for (int t = 0; t < 8; t++) UNPACK2(dash[2 * t], dash[2 * t + 1], accp[t]);
#pragma unroll
    for (int r = 0; r < 16; r++) dash[r] *= NORMALIZER;

    if (is_q) {
#pragma unroll
        for (int r = 0; r < 16; r++) {
            float v = dash[r];
            for (int off = 16; off; off >>= 1)
                v = fmaxf(v, __shfl_xor_sync(0xffffffffu, v, off));
            if (lane == 0) red[wid * 16 + r] = v;
        }
        __syncthreads();
        if (tid < 16) {
            float m = red[tid];
            for (int w = 1; w < 8; w++) m = fmaxf(m, red[w * 16 + tid]);
            rmax_s[tid] = m;
        }
        __syncthreads();
#pragma unroll
        for (int r = 0; r < 16; r++)
            g_QP[(row0 + r) * 256 + tid] =
                RATIO * (__expf(dash[r] - diag_s[r] - rmax_s[r]) + EPSK);
    } else {
        float bm = dash[0];
#pragma unroll
        for (int r = 1; r < 16; r++) bm = fmaxf(bm, dash[r]);
        for (int off = 16; off; off >>= 1)
            bm = fmaxf(bm, __shfl_xor_sync(0xffffffffu, bm, off));
        if (lane == 0) red[wid] = bm;
        __syncthreads();
        if (tid == 0) {
            float m = red[0];
            for (int w = 1; w < 8; w++) m = fmaxf(m, red[w]);
            atomicMax(&g_kmax, ford(m));
        }
#pragma unroll
        for (int r = 0; r < 16; r++)
            g_KE[(row0 + r) * 256 + tid] = __expf(dash[r] - diag_s[r]);   // E
    }
}

// ---------------- per-chunk local sums v4 (exactly as passing R14) -----------
__device__ __forceinline__ void cs4_mac(const float* __restrict__ kp_s,
                                        const float* __restrict__ v_s,
                                        int tl, int e, int mg,
                                        unsigned long long* acc) {
#pragma unroll 5
    for (int tt = 0; tt < tl; tt++) {
        float vsc = v_s[tt * 64 + e];
        unsigned long long vv; PACK2(vv, vsc, vsc);
        const float* kr = &kp_s[tt * 256 + mg * 32];
#pragma unroll
        for (int q = 0; q < 8; q++) {
            ulonglong2 kp2 = *(const ulonglong2*)&kr[q * 4];
            FMA2(acc[q * 2 + 0], kp2.x, vv);
            FMA2(acc[q * 2 + 1], kp2.y, vv);
        }
    }
}

__global__ __launch_bounds__(512, 2) void chunk_sums_kernel(const float* __restrict__ v) {
    __shared__ float kp_s[32 * 256];    // 32 KB
    __shared__ float v_s[32 * 64];      // 8 KB
    const int tid = threadIdx.x;
    const int e = tid & 63, mg = tid >> 6;
    const int slot = blockIdx.x, bh = blockIdx.y;
    const int t0  = slot ? (LCOND + (slot - 1) * LCH) : 0;
    const float gmax = fuord(g_kmax);
    const float rs = RATIO * __expf(-gmax);
    const float rk = RATIO * EPSK;

    unsigned long long acc[16];
#pragma unroll
    for (int c = 0; c < 16; c++) acc[c] = 0ull;
    float sk = 0.f;

    const float* Eb = g_KE + ((size_t)bh * NSEQ + t0) * 256;
    const float* vb = v    + ((size_t)bh * NSEQ + t0) * 64;

    if (slot == 0) {
        for (int base = 0; base < LCOND; base += 32) {
            __syncthreads();
            for (int idx = tid; idx < 32 * 256; idx += 512)
                kp_s[idx] = fmaf(Eb[(size_t)base * 256 + idx], rs, rk);
            for (int idx = tid; idx < 32 * 64; idx += 512)
                v_s[idx] = vb[(size_t)base * 64 + idx];
            __syncthreads();
            cs4_mac(kp_s, v_s, 32, e, mg, acc);
            if (tid < 256) {
#pragma unroll 8
                for (int tt = 0; tt < 32; tt++) sk += kp_s[tt * 256 + tid];
            }
        }
    } else {
        for (int idx = tid; idx < LCH * 256; idx += 512)
            kp_s[idx] = fmaf(Eb[idx], rs, rk);
        for (int idx = tid; idx < LCH * 64; idx += 512)
            v_s[idx] = vb[idx];
        __syncthreads();
        cs4_mac(kp_s, v_s, LCH, e, mg, acc);
        if (tid < 256) {
#pragma unroll 6
            for (int tt = 0; tt < LCH; tt++) sk += kp_s[tt * 256 + tid];
        }
    }

    if (tid < 256) g_Lk[((size_t)bh * NSLOT + slot) * 256 + tid] = sk;

    size_t ob = (((size_t)bh * NSLOT + slot) * 256 + mg * 32) * 64 + e;
#pragma unroll
    for (int p = 0; p < 16; p++) {
        float lo, hi; UNPACK2(lo, hi, acc[p]);
        g_Lctx[ob + (size_t)(2 * p    ) * 64] = lo;
        g_Lctx[ob + (size_t)(2 * p + 1) * 64] = hi;
    }
}

// ---------------- segmented exclusive prefix: pass A (segment sums) ----------
__global__ __launch_bounds__(256) void prefix_a_kernel() {
    const int g = blockIdx.x * 256 + threadIdx.x;   // 0..4351
    const int bh = blockIdx.y, seg = blockIdx.z;
    const int c0 = 1 + seg * 32;

    if (g < 256) {
        size_t base = (size_t)bh * NSLOT * 256 + g;
        float s = 0.f;
#pragma unroll
        for (int cb = 0; cb < 32; cb += 8) {
            float t[8];
#pragma unroll
            for (int u = 0; u < 8; u++)
                t[u] = g_Lk[base + (size_t)(c0 + cb + u) * 256];
#pragma unroll
            for (int u = 0; u < 8; u++) s += t[u];
        }
        g_SegLk[((size_t)bh * 256 + g) * 4 + seg] = s;
    } else {
        size_t base = (size_t)bh * NSLOT * 16384 + (size_t)(g - 256) * 4;
        float4 s = make_float4(0.f, 0.f, 0.f, 0.f);
#pragma unroll
        for (int cb = 0; cb < 32; cb += 8) {
            float4 t[8];
#pragma unroll
            for (int u = 0; u < 8; u++)
                t[u] = *(float4*)&g_Lctx[base + (size_t)(c0 + cb + u) * 16384];
#pragma unroll
            for (int u = 0; u < 8; u++) {
                s.x += t[u].x; s.y += t[u].y; s.z += t[u].z; s.w += t[u].w;
            }
        }
        *(float4*)&g_SegCtx[(((size_t)bh * 4096 + (g - 256)) * 4 + seg) * 4] = s;
    }
}

// ---------------- segmented exclusive prefix: pass B (scan within segment) ---
__global__ __launch_bounds__(256) void prefix_b_kernel() {
    const int g = blockIdx.x * 256 + threadIdx.x;   // 0..4351
    const int bh = blockIdx.y, seg = blockIdx.z;
    const int c0 = 1 + seg * 32;

    if (g < 256) {
        size_t base = (size_t)bh * NSLOT * 256 + g;
        float carry = g_Lk[base];                   // slot 0 (untouched by scan)
        for (int j = 0; j < seg; j++)
            carry += g_SegLk[((size_t)bh * 256 + g) * 4 + j];
#pragma unroll
        for (int cb = 0; cb < 32; cb += 8) {
            float t[8];
#pragma unroll
            for (int u = 0; u < 8; u++)
                t[u] = g_Lk[base + (size_t)(c0 + cb + u) * 256];
#pragma unroll
            for (int u = 0; u < 8; u++) {
                float nxt = t[u];
                g_Lk[base + (size_t)(c0 + cb + u) * 256] = carry;
                carry += nxt;
            }
        }
    } else {
        size_t base = (size_t)bh * NSLOT * 16384 + (size_t)(g - 256) * 4;
        float4 carry = *(float4*)&g_Lctx[base];     // slot 0
        for (int j = 0; j < seg; j++) {
            float4 s = *(float4*)&g_SegCtx[(((size_t)bh * 4096 + (g - 256)) * 4 + j) * 4];
            carry.x += s.x; carry.y += s.y; carry.z += s.z; carry.w += s.w;
        }
#pragma unroll
        for (int cb = 0; cb < 32; cb += 8) {
            float4 t[8];
#pragma unroll
            for (int u = 0; u < 8; u++)
                t[u] = *(float4*)&g_Lctx[base + (size_t)(c0 + cb + u) * 16384];
#pragma unroll
            for (int u = 0; u < 8; u++) {
                float4 nxt = t[u];
                *(float4*)&g_Lctx[base + (size_t)(c0 + cb + u) * 16384] = carry;
                carry.x += nxt.x; carry.y += nxt.y; carry.z += nxt.z; carry.w += nxt.w;
            }
        }
    }
}

// ---------------- conditioning-prefix output ---------------------------------
__global__ __launch_bounds__(128) void cond_out_kernel(float* __restrict__ out) {
    __shared__ float sden[4];
    const int tid = threadIdx.x;
    const int rl = tid >> 6, e = tid & 63;
    const int lane = tid & 31, wid = tid >> 5;
    const int bh = blockIdx.y;
    const int row = blockIdx.x * 2 + rl;
    const float* qrow = g_QP + ((size_t)bh * NSEQ + row) * 256;
    const float* lk0  = g_Lk   + (size_t)bh * NSLOT * 256;
    const float* ctx0 = g_Lctx + (size_t)bh * NSLOT * 16384;

    float p = 0.f;
    for (int m = e; m < 256; m += 64) p += qrow[m] * lk0[m];
    for (int off = 16; off; off >>= 1) p += __shfl_xor_sync(0xffffffffu, p, off);
    if (lane == 0) sden[wid] = p;
    __syncthreads();
    float den = sden[rl * 2] + sden[rl * 2 + 1];

    float acc = 0.f;
    for (int m4 = 0; m4 < 64; m4++) {
        float4 q4 = *(const float4*)&qrow[m4 * 4];
        acc += q4.x * ctx0[(m4 * 4 + 0) * 64 + e] + q4.y * ctx0[(m4 * 4 + 1) * 64 + e]
             + q4.z * ctx0[(m4 * 4 + 2) * 64 + e] + q4.w * ctx0[(m4 * 4 + 3) * 64 + e];
    }
    out[((size_t)bh * NSEQ + row) * 64 + e] = acc / den;
}

// ---------------- causal chunk output (kp = fma(E, rs, rk)) ------------------
#define QPAD 132
#define KPAD 133

__global__ __launch_bounds__(256) void causal_out_kernel(const float* __restrict__ v,
                                                         float* __restrict__ out) {
    __shared__ float q_s[LCH * QPAD];   // 15.84 KB
    __shared__ float k_s[LCH * KPAD];   // 15.96 KB
    __shared__ float v_s[LCH * 64];     // 7.5 KB
    __shared__ float A[32 * 32];
    __shared__ float ck[256];
    __shared__ float dinv[32];

    const int tid = threadIdx.x, lane = tid & 31, w = tid >> 5;
    const int ci = blockIdx.x, bh = blockIdx.y;
    const int t0 = LCOND + ci * LCH;
    const int slot = ci + 1;
    const float gmax = fuord(g_kmax);
    const float rs = RATIO * __expf(-gmax);
    const float rk = RATIO * EPSK;

    const float* qb = g_QP + ((size_t)bh * NSEQ + t0) * 256;
    const float* kb = g_KE + ((size_t)bh * NSEQ + t0) * 256;
    const float* vb = v    + ((size_t)bh * NSEQ + t0) * 64;
    const float* ctxc = g_Lctx + ((size_t)bh * NSLOT + slot) * 16384;

    for (int idx = tid; idx < LCH * 64; idx += 256) v_s[idx] = vb[idx];
    ck[tid] = g_Lk[((size_t)bh * NSLOT + slot) * 256 + tid];

    float a0 = 0.f, a1 = 0.f, a2 = 0.f, a3 = 0.f;
    float pden[4] = {0.f, 0.f, 0.f, 0.f};
    const int g = tid >> 6, e = tid & 63;
    float acc[8];
#pragma unroll
    for (int r = 0; r < 8; r++) acc[r] = 0.f;

    const int klane = (lane < LCH) ? lane : (LCH - 1);

    for (int mt = 0; mt < 2; mt++) {
        const int m0 = mt * 128;
        __syncthreads();
        for (int idx = tid; idx < LCH * 128; idx += 256) {
            int i = idx >> 7, ml = idx & 127;
            q_s[i * QPAD + ml] = qb[i * 256 + m0 + ml];
            k_s[i * KPAD + ml] = fmaf(kb[i * 256 + m0 + ml], rs, rk);
        }
        __syncthreads();

        {
            const float* krow = &k_s[klane * KPAD];
            const int iA = w, iB = w + 8, iC = w + 16, iD = (w + 24 < LCH) ? w + 24 : 0;
#pragma unroll 8
            for (int m4 = 0; m4 < 32; m4++) {
                float k0 = krow[m4 * 4 + 0], k1 = krow[m4 * 4 + 1];
                float k2 = krow[m4 * 4 + 2], k3 = krow[m4 * 4 + 3];
                float4 qA = *(const float4*)&q_s[iA * QPAD + m4 * 4];
                float4 qB = *(const float4*)&q_s[iB * QPAD + m4 * 4];
                float4 qC = *(const float4*)&q_s[iC * QPAD + m4 * 4];
                float4 qD = *(const float4*)&q_s[iD * QPAD + m4 * 4];
                a0 += qA.x * k0 + qA.y * k1 + qA.z * k2 + qA.w * k3;
                a1 += qB.x * k0 + qB.y * k1 + qB.z * k2 + qB.w * k3;
                a2 += qC.x * k0 + qC.y * k1 + qC.z * k2 + qC.w * k3;
                a3 += qD.x * k0 + qD.y * k1 + qD.z * k2 + qD.w * k3;
            }
        }

#pragma unroll
        for (int r = 0; r < 4; r++) {
            int i = w + 8 * r;
            if (i < LCH) {
                float p = 0.f;
                for (int ml = lane; ml < 128; ml += 32)
                    p += q_s[i * QPAD + ml] * (ck[m0 + ml] + EPSC);
                pden[r] += p;
            }
        }

        for (int m4 = 0; m4 < 32; m4++) {
            float c0 = ctxc[(m0 + m4 * 4 + 0) * 64 + e];
            float c1 = ctxc[(m0 + m4 * 4 + 1) * 64 + e];
            float c2 = ctxc[(m0 + m4 * 4 + 2) * 64 + e];
            float c3 = ctxc[(m0 + m4 * 4 + 3) * 64 + e];
#pragma unroll
            for (int r = 0; r < 8; r++) {
                int i = g + 4 * r;
                if (i < LCH) {
                    float4 q4 = *(const float4*)&q_s[i * QPAD + m4 * 4];
                    acc[r] += q4.x * c0 + q4.y * c1 + q4.z * c2 + q4.w * c3;
                }
            }
        }
    }

    if (lane < LCH) {
        A[(w     ) * 32 + lane] = a0;
        A[(w +  8) * 32 + lane] = a1;
        A[(w + 16) * 32 + lane] = a2;
        if (w + 24 < LCH) A[(w + 24) * 32 + lane] = a3;
    }
    __syncthreads();

#pragma unroll
    for (int r = 0; r < 4; r++) {
        int i = w + 8 * r;
        if (i < LCH) {
            float p = pden[r];
            if (lane <= i) p += A[i * 32 + lane];
            for (int off = 16; off; off >>= 1) p += __shfl_xor_sync(0xffffffffu, p, off);
            if (lane == 0) dinv[i] = 1.f / p;
        }
    }
    __syncthreads();

#pragma unroll
    for (int r = 0; r < 8; r++) {
        int i = g + 4 * r;
        if (i >= LCH) continue;
        float o = acc[r];
        for (int j = 0; j <= i; j++) o += A[i * 32 + j] * v_s[j * 64 + e];
        out[((size_t)bh * NSEQ + t0 + i) * 64 + e] = o * dinv[i];
    }
}

// ---------------- launch ------------------------------------------------------
extern "C" void kernel_launch(void* const* d_in, const int* in_sizes, int n_in,
                              void* d_out, int out_size) {
    (void)in_sizes; (void)n_in; (void)out_size;
    const float* q    = (const float*)d_in[0];
    const float* k    = (const float*)d_in[1];
    const float* v    = (const float*)d_in[2];
    const float* proj = (const float*)d_in[3];
    float* out = (float*)d_out;

    init_kernel<<<1, 1>>>();
    feat_kernel       <<<dim3(4096, 2), 256>>>(q, k, proj);
    chunk_sums_kernel <<<dim3(NSLOT, BHN), 512>>>(v);
    prefix_a_kernel   <<<dim3(17, BHN, 4), 256>>>();
    prefix_b_kernel   <<<dim3(17, BHN, 4), 256>>>();
    cond_out_kernel   <<<dim3(128, BHN), 128>>>(out);
    causal_out_kernel <<<dim3(NCHUNK, BHN), 256>>>(v, out);
}